// round 11
// baseline (speedup 1.0000x reference)
#include <cuda_runtime.h>

// Shapes (fixed per reference setup_inputs)
#define L_ 12
#define B_ 16
#define H_ 16
#define S_ 577
#define N_ 576      // spatial tokens (S-1)
#define D_ 1024
#define K_ 115      // int(576 * 0.2)

#define ROWS_ 4
#define CHUNKS_ ((K_ + ROWS_ - 1) / ROWS_)   // 29
#define TOTAL_BLOCKS_ (L_ * B_ * CHUNKS_)    // 5568

#define SLICES_ 18                            // token slices per batch
#define SLICE_TOK_ 32                         // tokens per slice (18*32 = 576)
#define TPT_ 8                                // threads cooperating per token
#define TOPK_BLOCKS_ (B_ * SLICES_)           // 288

// Device-global scratch + sync state (no allocation allowed).
// All sync state is returned to 0 by the end of every launch -> graph-replay safe.
__device__ int g_topk[B_ * K_];
__device__ int g_done = 0;              // topk completion counter
__device__ volatile int g_flag = 0;     // indices-ready flag
__device__ int g_gdone = 0;             // gather completion counter

// ---------------------------------------------------------------------------
// Fused kernel.
//   Blocks 0..287: compute exact top-K (rank counting) for their (batch, slice),
//     publish g_topk, last arrival resets g_done and raises g_flag.
//   All blocks: spin on g_flag (wave-1 residency >= 288 producer blocks, so no
//     deadlock), then gather 4 selected K/V rows (float4, streaming).
//   Last gather arrival resets g_gdone and g_flag for the next graph replay.
// Comparator (v>my)||(v==my && j<t) reproduces jax.lax.top_k ordering
// (desc value, asc index on ties) with unique ranks -> race-free writes.
// ---------------------------------------------------------------------------
__global__ void __launch_bounds__(256) fused_kernel(const float* __restrict__ key,
                                                    const float* __restrict__ val,
                                                    const float* __restrict__ attn,
                                                    float* __restrict__ out) {
    const int bid = blockIdx.x;
    const int tid = threadIdx.x;

    // ---------------- Phase A: top-K (first 288 blocks) ----------------
    if (bid < TOPK_BLOCKS_) {
        __shared__ __align__(16) float sc[N_];
        const int b = bid / SLICES_;
        const int s = bid % SLICES_;

        // scores for the whole batch (identical fp32 order in every block)
        const float* bbase = attn + (size_t)b * H_ * S_ * S_;
        for (int t = tid; t < N_; t += 256) {
            float sum = 0.0f;
            const float* p = bbase + (t + 1);
            #pragma unroll
            for (int h = 0; h < H_; ++h)
                sum += __ldg(p + (size_t)h * (S_ * S_));
            sc[t] = sum;
        }
        __syncthreads();

        // rank 32 tokens of this slice, 8 threads per token
        const int tok  = s * SLICE_TOK_ + (tid >> 3);
        const int part = tid & (TPT_ - 1);
        const float my = sc[tok];

        int rank = 0;
        #pragma unroll 8
        for (int j = part; j < N_; j += TPT_) {       // 72 iterations
            const float v = sc[j];
            rank += (v > my) || (v == my && j < tok);
        }
        #pragma unroll
        for (int off = TPT_ / 2; off > 0; off >>= 1)
            rank += __shfl_down_sync(0xffffffffu, rank, off, TPT_);

        if (part == 0 && rank < K_)
            g_topk[b * K_ + rank] = tok;

        // publish: last topk block resets g_done and raises the flag
        __syncthreads();
        if (tid == 0) {
            __threadfence();
            const int old = atomicAdd(&g_done, 1);
            if (old == TOPK_BLOCKS_ - 1) {
                g_done = 0;
                __threadfence();
                g_flag = 1;
            }
        }
    }

    // ---------------- Barrier: wait for indices ----------------
    if (tid == 0) {
        while (g_flag == 0)
            __nanosleep(64);
    }
    __syncthreads();
    __threadfence();   // order subsequent g_topk reads after flag observation

    // ---------------- Phase B: gather 4 K/V rows ----------------
    const int chunk = bid % CHUNKS_;
    const int b     = (bid / CHUNKS_) % B_;
    const int l     = bid / (CHUNKS_ * B_);
    const int k0    = chunk * ROWS_;

    const size_t src_base = (((size_t)l * B_ + b) * S_) * D_;
    const size_t dst_base = (((size_t)l * B_ + b) * K_) * (size_t)D_;
    const size_t val_out_base = (size_t)L_ * B_ * K_ * D_;

    int src_s[ROWS_];
    #pragma unroll
    for (int r = 0; r < ROWS_; ++r) {
        const int k = k0 + r;
        src_s[r] = (k < K_) ? (g_topk[b * K_ + k] + 1) : -1;
    }

    float4 kr[ROWS_], vr[ROWS_];
    #pragma unroll
    for (int r = 0; r < ROWS_; ++r) {
        if (src_s[r] >= 0) {
            const float* ksrc = key + src_base + (size_t)src_s[r] * D_;
            const float* vsrc = val + src_base + (size_t)src_s[r] * D_;
            kr[r] = __ldcs(reinterpret_cast<const float4*>(ksrc) + tid);
            vr[r] = __ldcs(reinterpret_cast<const float4*>(vsrc) + tid);
        }
    }

    #pragma unroll
    for (int r = 0; r < ROWS_; ++r) {
        const int k = k0 + r;
        if (src_s[r] >= 0) {
            float* kdst = out + dst_base + (size_t)k * D_;
            float* vdst = out + val_out_base + dst_base + (size_t)k * D_;
            __stcs(reinterpret_cast<float4*>(kdst) + tid, kr[r]);
            __stcs(reinterpret_cast<float4*>(vdst) + tid, vr[r]);
        }
    }

    // ---------------- Epilogue: reset sync state for next replay ----------------
    __syncthreads();
    if (tid == 0) {
        const int old = atomicAdd(&g_gdone, 1);
        if (old == TOTAL_BLOCKS_ - 1) {
            g_gdone = 0;
            __threadfence();
            g_flag = 0;   // everyone already observed flag==1 before incrementing
        }
    }
}

extern "C" void kernel_launch(void* const* d_in, const int* in_sizes, int n_in,
                              void* d_out, int out_size) {
    const float* key  = (const float*)d_in[0];  // (12,16,577,1024) f32
    const float* val  = (const float*)d_in[1];  // (12,16,577,1024) f32
    const float* attn = (const float*)d_in[2];  // (16,16,577,577)  f32
    float* out = (float*)d_out;                 // keys then values, each (12,16,115,1024)

    fused_kernel<<<TOTAL_BLOCKS_, 256>>>(key, val, attn, out);
}

// round 14
// speedup vs baseline: 1.1813x; 1.1813x over previous
#include <cuda_runtime.h>

// Shapes (fixed per reference setup_inputs)
#define L_ 12
#define B_ 16
#define H_ 16
#define S_ 577
#define N_ 576      // spatial tokens (S-1)
#define D_ 1024
#define K_ 115      // int(576 * 0.2)

#define ROWS_ 4
#define CHUNKS_ ((K_ + ROWS_ - 1) / ROWS_)   // 29

#define SLICES_ 18                            // token slices per batch
#define SLICE_TOK_ 32                         // tokens per slice (18*32 = 576)
#define TPT_ 8                                // threads cooperating per token

// Scratch: top-k indices per batch (device global — no allocation allowed)
__device__ int g_topk[B_ * K_];

// ---------------------------------------------------------------------------
// Kernel 1: distributed exact top-K via rank counting (R6 structure).
// Ends with griddepcontrol.launch_dependents so the PDL-launched gather
// kernel's wait gate opens the moment all topk CTAs have published.
// Comparator (v>my)||(v==my && j<t) reproduces jax.lax.top_k ordering
// (desc value, asc index on ties) with unique ranks -> race-free writes.
// ---------------------------------------------------------------------------
__global__ void __launch_bounds__(256) topk_kernel(const float* __restrict__ attn) {
    __shared__ __align__(16) float sc[N_];
    const int b   = blockIdx.x / SLICES_;
    const int s   = blockIdx.x % SLICES_;
    const int tid = threadIdx.x;

    // Phase 1: scores for the whole batch (identical fp32 order in every block
    // -> bitwise-identical scores -> consistent unique ranks)
    const float* bbase = attn + (size_t)b * H_ * S_ * S_;
    for (int t = tid; t < N_; t += 256) {
        float sum = 0.0f;
        const float* p = bbase + (t + 1);
        #pragma unroll
        for (int h = 0; h < H_; ++h)
            sum += __ldg(p + (size_t)h * (S_ * S_));
        sc[t] = sum;
    }
    __syncthreads();

    // Phase 2: rank 32 tokens of this slice, 8 threads per token.
    // float4 shared loads: 18 LDS.128 per thread instead of 72 scalar LDS.
    const int tok  = s * SLICE_TOK_ + (tid >> 3);   // tid/8 in 0..31
    const int part = tid & (TPT_ - 1);              // 0..7
    const float my = sc[tok];

    const float4* sc4 = reinterpret_cast<const float4*>(sc);
    int rank = 0;
    #pragma unroll
    for (int m = 0; m < (N_ / 4) / TPT_; ++m) {     // 18 iterations
        const int i = part + m * TPT_;
        const float4 v = sc4[i];
        const int j = 4 * i;
        rank += (v.x > my) || (v.x == my && (j + 0) < tok);
        rank += (v.y > my) || (v.y == my && (j + 1) < tok);
        rank += (v.z > my) || (v.z == my && (j + 2) < tok);
        rank += (v.w > my) || (v.w == my && (j + 3) < tok);
    }
    #pragma unroll
    for (int off = TPT_ / 2; off > 0; off >>= 1)
        rank += __shfl_down_sync(0xffffffffu, rank, off, TPT_);

    if (part == 0 && rank < K_)
        g_topk[b * K_ + rank] = tok;

    // Publish, then open the gate for the dependent (PDL) gather kernel.
    __threadfence();
    asm volatile("griddepcontrol.launch_dependents;");
}

// ---------------------------------------------------------------------------
// Kernel 2: gather selected K/V rows, 4 rows per block (at HBM roofline).
// Launched with programmaticStreamSerialization: blocks pre-launch and park
// at griddepcontrol.wait (HW gate, no L2 polling) until topk publishes.
// ---------------------------------------------------------------------------
__global__ void __launch_bounds__(256) gather_kernel(const float* __restrict__ key,
                                                     const float* __restrict__ val,
                                                     float* __restrict__ out) {
    asm volatile("griddepcontrol.wait;");

    const int chunk = blockIdx.x % CHUNKS_;
    const int b     = (blockIdx.x / CHUNKS_) % B_;
    const int l     = blockIdx.x / (CHUNKS_ * B_);
    const int k0    = chunk * ROWS_;
    const int t     = threadIdx.x;             // 0..255

    const size_t src_base = (((size_t)l * B_ + b) * S_) * D_;
    const size_t dst_base = (((size_t)l * B_ + b) * K_) * (size_t)D_;
    const size_t val_out_base = (size_t)L_ * B_ * K_ * D_;

    int src_s[ROWS_];
    #pragma unroll
    for (int r = 0; r < ROWS_; ++r) {
        const int k = k0 + r;
        src_s[r] = (k < K_) ? (g_topk[b * K_ + k] + 1) : -1;
    }

    float4 kr[ROWS_], vr[ROWS_];
    #pragma unroll
    for (int r = 0; r < ROWS_; ++r) {
        if (src_s[r] >= 0) {
            const float* ksrc = key + src_base + (size_t)src_s[r] * D_;
            const float* vsrc = val + src_base + (size_t)src_s[r] * D_;
            kr[r] = __ldcs(reinterpret_cast<const float4*>(ksrc) + t);
            vr[r] = __ldcs(reinterpret_cast<const float4*>(vsrc) + t);
        }
    }

    #pragma unroll
    for (int r = 0; r < ROWS_; ++r) {
        const int k = k0 + r;
        if (src_s[r] >= 0) {
            float* kdst = out + dst_base + (size_t)k * D_;
            float* vdst = out + val_out_base + dst_base + (size_t)k * D_;
            __stcs(reinterpret_cast<float4*>(kdst) + t, kr[r]);
            __stcs(reinterpret_cast<float4*>(vdst) + t, vr[r]);
        }
    }
}

extern "C" void kernel_launch(void* const* d_in, const int* in_sizes, int n_in,
                              void* d_out, int out_size) {
    const float* key  = (const float*)d_in[0];  // (12,16,577,1024) f32
    const float* val  = (const float*)d_in[1];  // (12,16,577,1024) f32
    const float* attn = (const float*)d_in[2];  // (16,16,577,577)  f32
    float* out = (float*)d_out;                 // keys then values, each (12,16,115,1024)

    topk_kernel<<<B_ * SLICES_, 256>>>(attn);

    // Gather via Programmatic Dependent Launch: overlaps its launch with the
    // topk tail; blocks gate on griddepcontrol.wait instead of a node edge.
    cudaLaunchConfig_t cfg = {};
    cfg.gridDim  = dim3(L_ * B_ * CHUNKS_, 1, 1);
    cfg.blockDim = dim3(256, 1, 1);
    cfg.dynamicSmemBytes = 0;
    cudaLaunchAttribute attrs[1];
    attrs[0].id = cudaLaunchAttributeProgrammaticStreamSerialization;
    attrs[0].val.programmaticStreamSerializationAllowed = 1;
    cfg.attrs = attrs;
    cfg.numAttrs = 1;
    cudaLaunchKernelEx(&cfg, gather_kernel, key, val, (float*)d_out);
}